// round 15
// baseline (speedup 1.0000x reference)
#include <cuda_runtime.h>
#include <cuda_fp16.h>
#include <cstdint>
#include <cstddef>

#define M_TOTAL 4096
#define N_TOTAL 16384
#define K_TOTAL 4096
#define BM 128
#define BN 128
#define BK 64
#define KT (K_TOTAL / BK)               // 64
#define STAGES 3
#define A_STAGE_BYTES (BM * BK * 2)     // 16 KB
#define B_STAGE_BYTES (BN * BK * 2)     // 16 KB
#define STAGE_BYTES (A_STAGE_BYTES + B_STAGE_BYTES)   // 32 KB
#define SMEM_TOTAL (STAGES * STAGE_BYTES)             // 96 KB

#define X_CHUNKS (M_TOTAL * (size_t)K_TOTAL / 4)      // float4 count
#define W_CHUNKS ((size_t)N_TOTAL * K_TOTAL / 4)      // int4 count

// fp16 scratch (pre-dequantized). __device__ globals are the sanctioned scratch path.
__device__ __align__(1024) __half g_Xh[M_TOTAL * (size_t)K_TOTAL];   // 32 MB
__device__ __align__(1024) __half g_Wh[(size_t)N_TOTAL * K_TOTAL];   // 128 MB

// ---------------- helpers ----------------
__device__ __forceinline__ uint32_t smem_u32(const void* p) {
    uint32_t a;
    asm("{ .reg .u64 t; cvta.to.shared.u64 t, %1; cvt.u32.u64 %0, t; }" : "=r"(a) : "l"(p));
    return a;
}

__device__ __forceinline__ void ldsm_x4(uint32_t& r0, uint32_t& r1, uint32_t& r2, uint32_t& r3,
                                        uint32_t addr) {
    asm volatile("ldmatrix.sync.aligned.m8n8.x4.shared.b16 {%0,%1,%2,%3}, [%4];"
                 : "=r"(r0), "=r"(r1), "=r"(r2), "=r"(r3) : "r"(addr));
}

__device__ __forceinline__ void mma16816(float* c,
                                         uint32_t a0, uint32_t a1, uint32_t a2, uint32_t a3,
                                         uint32_t b0, uint32_t b1) {
    asm volatile(
        "mma.sync.aligned.m16n8k16.row.col.f32.f16.f16.f32 "
        "{%0,%1,%2,%3}, {%4,%5,%6,%7}, {%8,%9}, {%0,%1,%2,%3};"
        : "+f"(c[0]), "+f"(c[1]), "+f"(c[2]), "+f"(c[3])
        : "r"(a0), "r"(a1), "r"(a2), "r"(a3), "r"(b0), "r"(b1));
}

// ---------------- fused conversion kernel (32B per stream per thread) ----------------
__global__ void __launch_bounds__(256) cvt_all_kernel(const float4* __restrict__ x,
                                                      const int4* __restrict__ w,
                                                      const float* __restrict__ zp) {
    const size_t i = ((size_t)blockIdx.x * blockDim.x + threadIdx.x) * 2;   // 2 chunks/thread
    const float z = __ldg(zp);
#pragma unroll
    for (int j = 0; j < 2; j++) {
        int4 q = w[i + j];
        __half2 h0 = __floats2half2_rn((float)q.x - z, (float)q.y - z);  // exact in fp16
        __half2 h1 = __floats2half2_rn((float)q.z - z, (float)q.w - z);
        uint2 o;
        o.x = *reinterpret_cast<uint32_t*>(&h0);
        o.y = *reinterpret_cast<uint32_t*>(&h1);
        *reinterpret_cast<uint2*>(&g_Wh[(i + j) * 4]) = o;
    }
    if (i < X_CHUNKS) {
#pragma unroll
        for (int j = 0; j < 2; j++) {
            float4 v = x[i + j];
            __half2 h0 = __floats2half2_rn(v.x, v.y);
            __half2 h1 = __floats2half2_rn(v.z, v.w);
            uint2 o;
            o.x = *reinterpret_cast<uint32_t*>(&h0);
            o.y = *reinterpret_cast<uint32_t*>(&h1);
            *reinterpret_cast<uint2*>(&g_Xh[(i + j) * 4]) = o;
        }
    }
}

// ---------------- pipelined HMMA GEMM (R10 config + ldsm/cp.async overlap) ----------------
// C[4096,16384] = Xh @ Wh^T (both K-major), *scale + bias
__global__ void __launch_bounds__(256, 2)
gemm_hmma_kernel(const float* __restrict__ scale_p,
                 const float* __restrict__ bias,
                 float* __restrict__ out)
{
    extern __shared__ __align__(1024) char smem[];
    const uint32_t smem_base = smem_u32(smem);
    const int tid  = threadIdx.x;
    const int wid  = tid >> 5;
    const int lane = tid & 31;
    const int mw = wid & 3;          // 4 warps along M (32 rows each)
    const int nw = wid >> 2;         // 2 warps along N (64 cols each)

    // CTA rasterization swizzle: 16 groups of 16x16 tiles -> squarer wave footprint
    const int bid = blockIdx.x + (blockIdx.y << 5);   // 0..4095
    const int lid = bid & 255;
    const int gid = bid >> 8;                          // 0..15
    const int mtile = ((gid & 1) << 4) + (lid & 15);   // 0..31
    const int ntile = ((gid >> 1) << 4) + (lid >> 4);  // 0..127

    const __half* gA = g_Xh + (size_t)mtile * BM * K_TOTAL;
    const __half* gB = g_Wh + (size_t)ntile * BN * K_TOTAL;

    auto load_stage = [&](int kt, int stage) {
        const uint32_t sA = smem_base + stage * STAGE_BYTES;
        const uint32_t sB = sA + A_STAGE_BYTES;
        const char* pA = (const char*)gA + (size_t)kt * (BK * 2);
        const char* pB = (const char*)gB + (size_t)kt * (BK * 2);
#pragma unroll
        for (int i = 0; i < 4; i++) {
            int ci  = i * 256 + tid;
            int row = ci >> 3;                 // 0..127
            int c   = ci & 7;                  // 16B chunk within 128B row
            uint32_t off = (uint32_t)(row * 128 + c * 16);
            uint32_t sw  = off ^ ((off >> 3) & 0x70);
            asm volatile("cp.async.cg.shared.global [%0], [%1], 16;"
                         :: "r"(sA + sw), "l"(pA + (size_t)row * (K_TOTAL * 2) + c * 16));
            asm volatile("cp.async.cg.shared.global [%0], [%1], 16;"
                         :: "r"(sB + sw), "l"(pB + (size_t)row * (K_TOTAL * 2) + c * 16));
        }
        asm volatile("cp.async.commit_group;" ::: "memory");
    };

    // ldmatrix lane address prep (tile-relative): addr = base + ((lin + ks*32) ^ xor)
    uint32_t aLin[2], aXor[2];
#pragma unroll
    for (int t = 0; t < 2; t++) {
        int row = mw * 32 + t * 16 + (lane & 15);
        aLin[t] = (uint32_t)(row * 128 + (lane >> 4) * 16);
        aXor[t] = (uint32_t)((row * 16) & 0x70);
    }
    uint32_t bLin[4], bXor[4];
#pragma unroll
    for (int u = 0; u < 4; u++) {
        int g = lane >> 3, r = lane & 7;
        int row = nw * 64 + u * 16 + ((g >> 1) << 3) + r;
        bLin[u] = (uint32_t)(row * 128 + (g & 1) * 16);
        bXor[u] = (uint32_t)((row * 16) & 0x70);
    }

    float acc[2][8][4];
#pragma unroll
    for (int t = 0; t < 2; t++)
#pragma unroll
        for (int n = 0; n < 8; n++)
#pragma unroll
            for (int j = 0; j < 4; j++) acc[t][n][j] = 0.0f;

    load_stage(0, 0);
    load_stage(1, 1);

    for (int kt = 0; kt < KT; kt++) {
        asm volatile("cp.async.wait_group %0;" :: "n"(STAGES - 2) : "memory");
        __syncthreads();

        const uint32_t sA = smem_base + (kt % STAGES) * STAGE_BYTES;
        const uint32_t sB = sA + A_STAGE_BYTES;

        // --- ks=0 fragment loads FIRST: their latency drains behind the cp.async burst ---
        uint32_t a[2][4], b[4][4];
#pragma unroll
        for (int t = 0; t < 2; t++)
            ldsm_x4(a[t][0], a[t][1], a[t][2], a[t][3], sA + (aLin[t] ^ aXor[t]));
#pragma unroll
        for (int u = 0; u < 4; u++)
            ldsm_x4(b[u][0], b[u][1], b[u][2], b[u][3], sB + (bLin[u] ^ bXor[u]));

        // --- issue next stage's prefetch (writes a different stage; barrier above protects it) ---
        const int pf = kt + STAGES - 1;
        if (pf < KT) {
            load_stage(pf, pf % STAGES);
        } else {
            asm volatile("cp.async.commit_group;" ::: "memory");
        }

#pragma unroll
        for (int ks = 0; ks < 4; ks++) {
            if (ks > 0) {
#pragma unroll
                for (int t = 0; t < 2; t++)
                    ldsm_x4(a[t][0], a[t][1], a[t][2], a[t][3],
                            sA + ((aLin[t] + ks * 32) ^ aXor[t]));
#pragma unroll
                for (int u = 0; u < 4; u++)
                    ldsm_x4(b[u][0], b[u][1], b[u][2], b[u][3],
                            sB + ((bLin[u] + ks * 32) ^ bXor[u]));
            }
#pragma unroll
            for (int t = 0; t < 2; t++)
#pragma unroll
                for (int n = 0; n < 8; n++) {
                    uint32_t b0 = b[n >> 1][(n & 1) * 2 + 0];
                    uint32_t b1 = b[n >> 1][(n & 1) * 2 + 1];
                    mma16816(acc[t][n], a[t][0], a[t][1], a[t][2], a[t][3], b0, b1);
                }
        }
    }

    // epilogue: out = acc*scale + bias
    const float scl = __ldg(scale_p);
    const int rbase = mtile * BM + mw * 32 + (lane >> 2);
    const int cbase = ntile * BN + nw * 64 + (lane & 3) * 2;
#pragma unroll
    for (int t = 0; t < 2; t++) {
        const int r0 = rbase + t * 16;
#pragma unroll
        for (int n = 0; n < 8; n++) {
            const int col = cbase + n * 8;
            const float2 bb = *reinterpret_cast<const float2*>(bias + col);
            float2 v0, v1;
            v0.x = acc[t][n][0] * scl + bb.x;
            v0.y = acc[t][n][1] * scl + bb.y;
            v1.x = acc[t][n][2] * scl + bb.x;
            v1.y = acc[t][n][3] * scl + bb.y;
            *reinterpret_cast<float2*>(out + (size_t)r0 * N_TOTAL + col) = v0;
            *reinterpret_cast<float2*>(out + (size_t)(r0 + 8) * N_TOTAL + col) = v1;
        }
    }
}

// ---------------- launch ----------------
extern "C" void kernel_launch(void* const* d_in, const int* in_sizes, int n_in,
                              void* d_out, int out_size) {
    (void)in_sizes; (void)n_in; (void)out_size;
    const float* x     = (const float*)d_in[0];
    const int*   w     = (const int*)  d_in[1];
    const float* scale = (const float*)d_in[2];
    const float* zp    = (const float*)d_in[3];
    const float* bias  = (const float*)d_in[4];
    float* out = (float*)d_out;

    cvt_all_kernel<<<(unsigned)(W_CHUNKS / 512), 256>>>((const float4*)x, (const int4*)w, zp);

    static int smem_set = 0;
    if (!smem_set) {
        cudaFuncSetAttribute(gemm_hmma_kernel,
                             cudaFuncAttributeMaxDynamicSharedMemorySize, SMEM_TOTAL);
        smem_set = 1;
    }
    dim3 grid(M_TOTAL / BM, N_TOTAL / BN);
    gemm_hmma_kernel<<<grid, 256, SMEM_TOTAL>>>(scale, bias, out);
}

// round 16
// speedup vs baseline: 1.1149x; 1.1149x over previous
#include <cuda_runtime.h>
#include <cuda_fp16.h>
#include <cstdint>
#include <cstddef>

#define M_TOTAL 4096
#define N_TOTAL 16384
#define K_TOTAL 4096
#define BM 128
#define BN 128
#define BK 64
#define KT (K_TOTAL / BK)               // 64
#define STAGES 3
#define A_STAGE_BYTES (BM * BK * 2)     // 16 KB
#define B_STAGE_BYTES (BN * BK * 2)     // 16 KB
#define STAGE_BYTES (A_STAGE_BYTES + B_STAGE_BYTES)   // 32 KB
#define SMEM_TOTAL (STAGES * STAGE_BYTES)             // 96 KB

#define X_CHUNKS (M_TOTAL * (size_t)K_TOTAL / 4)      // float4 count
#define W_CHUNKS ((size_t)N_TOTAL * K_TOTAL / 4)      // int4 count

// fp16 scratch (pre-dequantized). __device__ globals are the sanctioned scratch path.
__device__ __align__(1024) __half g_Xh[M_TOTAL * (size_t)K_TOTAL];   // 32 MB
__device__ __align__(1024) __half g_Wh[(size_t)N_TOTAL * K_TOTAL];   // 128 MB

// ---------------- helpers ----------------
__device__ __forceinline__ uint32_t smem_u32(const void* p) {
    uint32_t a;
    asm("{ .reg .u64 t; cvta.to.shared.u64 t, %1; cvt.u32.u64 %0, t; }" : "=r"(a) : "l"(p));
    return a;
}

__device__ __forceinline__ void ldsm_x4(uint32_t& r0, uint32_t& r1, uint32_t& r2, uint32_t& r3,
                                        uint32_t addr) {
    asm volatile("ldmatrix.sync.aligned.m8n8.x4.shared.b16 {%0,%1,%2,%3}, [%4];"
                 : "=r"(r0), "=r"(r1), "=r"(r2), "=r"(r3) : "r"(addr));
}

__device__ __forceinline__ void mma16816(float* c,
                                         uint32_t a0, uint32_t a1, uint32_t a2, uint32_t a3,
                                         uint32_t b0, uint32_t b1) {
    asm volatile(
        "mma.sync.aligned.m16n8k16.row.col.f32.f16.f16.f32 "
        "{%0,%1,%2,%3}, {%4,%5,%6,%7}, {%8,%9}, {%0,%1,%2,%3};"
        : "+f"(c[0]), "+f"(c[1]), "+f"(c[2]), "+f"(c[3])
        : "r"(a0), "r"(a1), "r"(a2), "r"(a3), "r"(b0), "r"(b1));
}

// ---------------- fused conversion kernel (32B per stream per thread) ----------------
__global__ void __launch_bounds__(256) cvt_all_kernel(const float4* __restrict__ x,
                                                      const int4* __restrict__ w,
                                                      const float* __restrict__ zp) {
    const size_t i = ((size_t)blockIdx.x * blockDim.x + threadIdx.x) * 2;   // 2 chunks/thread
    const float z = __ldg(zp);
#pragma unroll
    for (int j = 0; j < 2; j++) {
        int4 q = w[i + j];
        __half2 h0 = __floats2half2_rn((float)q.x - z, (float)q.y - z);  // exact in fp16
        __half2 h1 = __floats2half2_rn((float)q.z - z, (float)q.w - z);
        uint2 o;
        o.x = *reinterpret_cast<uint32_t*>(&h0);
        o.y = *reinterpret_cast<uint32_t*>(&h1);
        *reinterpret_cast<uint2*>(&g_Wh[(i + j) * 4]) = o;
    }
    if (i < X_CHUNKS) {
#pragma unroll
        for (int j = 0; j < 2; j++) {
            float4 v = x[i + j];
            __half2 h0 = __floats2half2_rn(v.x, v.y);
            __half2 h1 = __floats2half2_rn(v.z, v.w);
            uint2 o;
            o.x = *reinterpret_cast<uint32_t*>(&h0);
            o.y = *reinterpret_cast<uint32_t*>(&h1);
            *reinterpret_cast<uint2*>(&g_Xh[(i + j) * 4]) = o;
        }
    }
}

// ---------------- pipelined HMMA GEMM (R10 config, proven best) ----------------
// C[4096,16384] = Xh[4096,4096] @ Wh[16384,4096]^T  (both K-major), *scale + bias
__global__ void __launch_bounds__(256, 2)
gemm_hmma_kernel(const float* __restrict__ scale_p,
                 const float* __restrict__ bias,
                 float* __restrict__ out)
{
    extern __shared__ __align__(1024) char smem[];
    const uint32_t smem_base = smem_u32(smem);
    const int tid  = threadIdx.x;
    const int wid  = tid >> 5;
    const int lane = tid & 31;
    const int mw = wid & 3;          // 4 warps along M (32 rows each)
    const int nw = wid >> 2;         // 2 warps along N (64 cols each)

    // CTA rasterization swizzle: 16 groups of 16x16 tiles -> squarer wave footprint
    const int bid = blockIdx.x + (blockIdx.y << 5);   // 0..4095
    const int lid = bid & 255;
    const int gid = bid >> 8;                          // 0..15
    const int mtile = ((gid & 1) << 4) + (lid & 15);   // 0..31
    const int ntile = ((gid >> 1) << 4) + (lid >> 4);  // 0..127

    const __half* gA = g_Xh + (size_t)mtile * BM * K_TOTAL;
    const __half* gB = g_Wh + (size_t)ntile * BN * K_TOTAL;

    auto load_stage = [&](int kt, int stage) {
        const uint32_t sA = smem_base + stage * STAGE_BYTES;
        const uint32_t sB = sA + A_STAGE_BYTES;
        const char* pA = (const char*)gA + (size_t)kt * (BK * 2);
        const char* pB = (const char*)gB + (size_t)kt * (BK * 2);
#pragma unroll
        for (int i = 0; i < 4; i++) {
            int ci  = i * 256 + tid;
            int row = ci >> 3;                 // 0..127
            int c   = ci & 7;                  // 16B chunk within 128B row
            uint32_t off = (uint32_t)(row * 128 + c * 16);
            uint32_t sw  = off ^ ((off >> 3) & 0x70);
            asm volatile("cp.async.cg.shared.global [%0], [%1], 16;"
                         :: "r"(sA + sw), "l"(pA + (size_t)row * (K_TOTAL * 2) + c * 16));
            asm volatile("cp.async.cg.shared.global [%0], [%1], 16;"
                         :: "r"(sB + sw), "l"(pB + (size_t)row * (K_TOTAL * 2) + c * 16));
        }
        asm volatile("cp.async.commit_group;" ::: "memory");
    };

    // ldmatrix lane address prep (tile-relative): addr = base + ((lin + ks*32) ^ xor)
    uint32_t aLin[2], aXor[2];
#pragma unroll
    for (int t = 0; t < 2; t++) {
        int row = mw * 32 + t * 16 + (lane & 15);
        aLin[t] = (uint32_t)(row * 128 + (lane >> 4) * 16);
        aXor[t] = (uint32_t)((row * 16) & 0x70);
    }
    uint32_t bLin[4], bXor[4];
#pragma unroll
    for (int u = 0; u < 4; u++) {
        int g = lane >> 3, r = lane & 7;
        int row = nw * 64 + u * 16 + ((g >> 1) << 3) + r;
        bLin[u] = (uint32_t)(row * 128 + (g & 1) * 16);
        bXor[u] = (uint32_t)((row * 16) & 0x70);
    }

    float acc[2][8][4];
#pragma unroll
    for (int t = 0; t < 2; t++)
#pragma unroll
        for (int n = 0; n < 8; n++)
#pragma unroll
            for (int j = 0; j < 4; j++) acc[t][n][j] = 0.0f;

    load_stage(0, 0);
    load_stage(1, 1);

    for (int kt = 0; kt < KT; kt++) {
        asm volatile("cp.async.wait_group %0;" :: "n"(STAGES - 2) : "memory");
        __syncthreads();

        const int pf = kt + STAGES - 1;
        if (pf < KT) {
            load_stage(pf, pf % STAGES);
        } else {
            asm volatile("cp.async.commit_group;" ::: "memory");
        }

        const uint32_t sA = smem_base + (kt % STAGES) * STAGE_BYTES;
        const uint32_t sB = sA + A_STAGE_BYTES;
#pragma unroll
        for (int ks = 0; ks < 4; ks++) {
            uint32_t a[2][4];
#pragma unroll
            for (int t = 0; t < 2; t++)
                ldsm_x4(a[t][0], a[t][1], a[t][2], a[t][3],
                        sA + ((aLin[t] + ks * 32) ^ aXor[t]));
            uint32_t b[4][4];
#pragma unroll
            for (int u = 0; u < 4; u++)
                ldsm_x4(b[u][0], b[u][1], b[u][2], b[u][3],
                        sB + ((bLin[u] + ks * 32) ^ bXor[u]));
#pragma unroll
            for (int t = 0; t < 2; t++)
#pragma unroll
                for (int n = 0; n < 8; n++) {
                    uint32_t b0 = b[n >> 1][(n & 1) * 2 + 0];
                    uint32_t b1 = b[n >> 1][(n & 1) * 2 + 1];
                    mma16816(acc[t][n], a[t][0], a[t][1], a[t][2], a[t][3], b0, b1);
                }
        }
    }

    // epilogue: out = acc*scale + bias
    const float scl = __ldg(scale_p);
    const int rbase = mtile * BM + mw * 32 + (lane >> 2);
    const int cbase = ntile * BN + nw * 64 + (lane & 3) * 2;
#pragma unroll
    for (int t = 0; t < 2; t++) {
        const int r0 = rbase + t * 16;
#pragma unroll
        for (int n = 0; n < 8; n++) {
            const int col = cbase + n * 8;
            const float2 bb = *reinterpret_cast<const float2*>(bias + col);
            float2 v0, v1;
            v0.x = acc[t][n][0] * scl + bb.x;
            v0.y = acc[t][n][1] * scl + bb.y;
            v1.x = acc[t][n][2] * scl + bb.x;
            v1.y = acc[t][n][3] * scl + bb.y;
            *reinterpret_cast<float2*>(out + (size_t)r0 * N_TOTAL + col) = v0;
            *reinterpret_cast<float2*>(out + (size_t)(r0 + 8) * N_TOTAL + col) = v1;
        }
    }
}

// ---------------- launch ----------------
extern "C" void kernel_launch(void* const* d_in, const int* in_sizes, int n_in,
                              void* d_out, int out_size) {
    (void)in_sizes; (void)n_in; (void)out_size;
    const float* x     = (const float*)d_in[0];
    const int*   w     = (const int*)  d_in[1];
    const float* scale = (const float*)d_in[2];
    const float* zp    = (const float*)d_in[3];
    const float* bias  = (const float*)d_in[4];
    float* out = (float*)d_out;

    cvt_all_kernel<<<(unsigned)(W_CHUNKS / 512), 256>>>((const float4*)x, (const int4*)w, zp);

    static int smem_set = 0;
    if (!smem_set) {
        cudaFuncSetAttribute(gemm_hmma_kernel,
                             cudaFuncAttributeMaxDynamicSharedMemorySize, SMEM_TOTAL);
        smem_set = 1;
    }
    dim3 grid(M_TOTAL / BM, N_TOTAL / BN);
    gemm_hmma_kernel<<<grid, 256, SMEM_TOTAL>>>(scale, bias, out);
}

// round 17
// speedup vs baseline: 1.1462x; 1.0280x over previous
#include <cuda_runtime.h>
#include <cuda_fp16.h>
#include <cstdint>
#include <cstddef>

#define M_TOTAL 4096
#define N_TOTAL 16384
#define K_TOTAL 4096
#define BM 128
#define BN 128
#define BK 64
#define KT (K_TOTAL / BK)               // 64
#define STAGES 3
#define A_STAGE_BYTES (BM * BK * 2)     // 16 KB
#define B_STAGE_BYTES (BN * BK * 2)     // 16 KB
#define STAGE_BYTES (A_STAGE_BYTES + B_STAGE_BYTES)   // 32 KB
#define SMEM_TOTAL (STAGES * STAGE_BYTES)             // 96 KB

#define X_CHUNKS (M_TOTAL * (size_t)K_TOTAL / 4)      // float4 count
#define W_CHUNKS ((size_t)N_TOTAL * K_TOTAL / 4)      // int4 count

// fp16 scratch (pre-dequantized). __device__ globals are the sanctioned scratch path.
__device__ __align__(1024) __half g_Xh[M_TOTAL * (size_t)K_TOTAL];   // 32 MB
__device__ __align__(1024) __half g_Wh[(size_t)N_TOTAL * K_TOTAL];   // 128 MB

// ---------------- helpers ----------------
__device__ __forceinline__ uint32_t smem_u32(const void* p) {
    uint32_t a;
    asm("{ .reg .u64 t; cvta.to.shared.u64 t, %1; cvt.u32.u64 %0, t; }" : "=r"(a) : "l"(p));
    return a;
}

__device__ __forceinline__ void ldsm_x4(uint32_t& r0, uint32_t& r1, uint32_t& r2, uint32_t& r3,
                                        uint32_t addr) {
    asm volatile("ldmatrix.sync.aligned.m8n8.x4.shared.b16 {%0,%1,%2,%3}, [%4];"
                 : "=r"(r0), "=r"(r1), "=r"(r2), "=r"(r3) : "r"(addr));
}

__device__ __forceinline__ void mma16816(float* c,
                                         uint32_t a0, uint32_t a1, uint32_t a2, uint32_t a3,
                                         uint32_t b0, uint32_t b1) {
    asm volatile(
        "mma.sync.aligned.m16n8k16.row.col.f32.f16.f16.f32 "
        "{%0,%1,%2,%3}, {%4,%5,%6,%7}, {%8,%9}, {%0,%1,%2,%3};"
        : "+f"(c[0]), "+f"(c[1]), "+f"(c[2]), "+f"(c[3])
        : "r"(a0), "r"(a1), "r"(a2), "r"(a3), "r"(b0), "r"(b1));
}

// ---------------- fused conversion kernel (32B per stream per thread) ----------------
__global__ void __launch_bounds__(256) cvt_all_kernel(const float4* __restrict__ x,
                                                      const int4* __restrict__ w,
                                                      const float* __restrict__ zp) {
    const size_t i = ((size_t)blockIdx.x * blockDim.x + threadIdx.x) * 2;   // 2 chunks/thread
    const float z = __ldg(zp);
#pragma unroll
    for (int j = 0; j < 2; j++) {
        int4 q = w[i + j];
        __half2 h0 = __floats2half2_rn((float)q.x - z, (float)q.y - z);  // exact in fp16
        __half2 h1 = __floats2half2_rn((float)q.z - z, (float)q.w - z);
        uint2 o;
        o.x = *reinterpret_cast<uint32_t*>(&h0);
        o.y = *reinterpret_cast<uint32_t*>(&h1);
        *reinterpret_cast<uint2*>(&g_Wh[(i + j) * 4]) = o;
    }
    if (i < X_CHUNKS) {
#pragma unroll
        for (int j = 0; j < 2; j++) {
            float4 v = x[i + j];
            __half2 h0 = __floats2half2_rn(v.x, v.y);
            __half2 h1 = __floats2half2_rn(v.z, v.w);
            uint2 o;
            o.x = *reinterpret_cast<uint32_t*>(&h0);
            o.y = *reinterpret_cast<uint32_t*>(&h1);
            *reinterpret_cast<uint2*>(&g_Xh[(i + j) * 4]) = o;
        }
    }
}

// ---------------- pipelined HMMA GEMM (R10 config, stage-unrolled x3) ----------------
// C[4096,16384] = Xh[4096,4096] @ Wh[16384,4096]^T  (both K-major), *scale + bias
__global__ void __launch_bounds__(256, 2)
gemm_hmma_kernel(const float* __restrict__ scale_p,
                 const float* __restrict__ bias,
                 float* __restrict__ out)
{
    extern __shared__ __align__(1024) char smem[];
    const uint32_t smem_base = smem_u32(smem);
    const int tid  = threadIdx.x;
    const int wid  = tid >> 5;
    const int lane = tid & 31;
    const int mw = wid & 3;          // 4 warps along M (32 rows each)
    const int nw = wid >> 2;         // 2 warps along N (64 cols each)

    // CTA rasterization swizzle: 16 groups of 16x16 tiles -> squarer wave footprint
    const int bid = blockIdx.x + (blockIdx.y << 5);   // 0..4095
    const int lid = bid & 255;
    const int gid = bid >> 8;                          // 0..15
    const int mtile = ((gid & 1) << 4) + (lid & 15);   // 0..31
    const int ntile = ((gid >> 1) << 4) + (lid >> 4);  // 0..127

    const __half* gA = g_Xh + (size_t)mtile * BM * K_TOTAL;
    const __half* gB = g_Wh + (size_t)ntile * BN * K_TOTAL;

    auto load_stage = [&](int kt, int stage) {
        const uint32_t sA = smem_base + stage * STAGE_BYTES;
        const uint32_t sB = sA + A_STAGE_BYTES;
        const char* pA = (const char*)gA + (size_t)kt * (BK * 2);
        const char* pB = (const char*)gB + (size_t)kt * (BK * 2);
#pragma unroll
        for (int i = 0; i < 4; i++) {
            int ci  = i * 256 + tid;
            int row = ci >> 3;                 // 0..127
            int c   = ci & 7;                  // 16B chunk within 128B row
            uint32_t off = (uint32_t)(row * 128 + c * 16);
            uint32_t sw  = off ^ ((off >> 3) & 0x70);
            asm volatile("cp.async.cg.shared.global [%0], [%1], 16;"
                         :: "r"(sA + sw), "l"(pA + (size_t)row * (K_TOTAL * 2) + c * 16));
            asm volatile("cp.async.cg.shared.global [%0], [%1], 16;"
                         :: "r"(sB + sw), "l"(pB + (size_t)row * (K_TOTAL * 2) + c * 16));
        }
        asm volatile("cp.async.commit_group;" ::: "memory");
    };

    // ldmatrix lane address prep (tile-relative): addr = base + ((lin + ks*32) ^ xor)
    uint32_t aLin[2], aXor[2];
#pragma unroll
    for (int t = 0; t < 2; t++) {
        int row = mw * 32 + t * 16 + (lane & 15);
        aLin[t] = (uint32_t)(row * 128 + (lane >> 4) * 16);
        aXor[t] = (uint32_t)((row * 16) & 0x70);
    }
    uint32_t bLin[4], bXor[4];
#pragma unroll
    for (int u = 0; u < 4; u++) {
        int g = lane >> 3, r = lane & 7;
        int row = nw * 64 + u * 16 + ((g >> 1) << 3) + r;
        bLin[u] = (uint32_t)(row * 128 + (g & 1) * 16);
        bXor[u] = (uint32_t)((row * 16) & 0x70);
    }

    float acc[2][8][4];
#pragma unroll
    for (int t = 0; t < 2; t++)
#pragma unroll
        for (int n = 0; n < 8; n++)
#pragma unroll
            for (int j = 0; j < 4; j++) acc[t][n][j] = 0.0f;

    // one pipeline iteration with COMPILE-TIME stage index
    auto iter = [&](int kt, const int stage) {
        asm volatile("cp.async.wait_group %0;" :: "n"(STAGES - 2) : "memory");
        __syncthreads();

        const int pf = kt + STAGES - 1;
        if (pf < KT) {
            load_stage(pf, (stage + STAGES - 1) % STAGES);   // folds to a constant
        } else {
            asm volatile("cp.async.commit_group;" ::: "memory");
        }

        const uint32_t sA = smem_base + stage * STAGE_BYTES; // constant offset
        const uint32_t sB = sA + A_STAGE_BYTES;
#pragma unroll
        for (int ks = 0; ks < 4; ks++) {
            uint32_t a[2][4];
#pragma unroll
            for (int t = 0; t < 2; t++)
                ldsm_x4(a[t][0], a[t][1], a[t][2], a[t][3],
                        sA + ((aLin[t] + ks * 32) ^ aXor[t]));
            uint32_t b[4][4];
#pragma unroll
            for (int u = 0; u < 4; u++)
                ldsm_x4(b[u][0], b[u][1], b[u][2], b[u][3],
                        sB + ((bLin[u] + ks * 32) ^ bXor[u]));
#pragma unroll
            for (int t = 0; t < 2; t++)
#pragma unroll
                for (int n = 0; n < 8; n++) {
                    uint32_t b0 = b[n >> 1][(n & 1) * 2 + 0];
                    uint32_t b1 = b[n >> 1][(n & 1) * 2 + 1];
                    mma16816(acc[t][n], a[t][0], a[t][1], a[t][2], a[t][3], b0, b1);
                }
        }
    };

    load_stage(0, 0);
    load_stage(1, 1);

    // KT = 64 = 3*21 + 1: 21 triples with constant stages, then one tail iter (stage 0)
#pragma unroll 1
    for (int kb = 0; kb < 63; kb += 3) {
        iter(kb + 0, 0);
        iter(kb + 1, 1);
        iter(kb + 2, 2);
    }
    iter(63, 0);

    // epilogue: out = acc*scale + bias
    const float scl = __ldg(scale_p);
    const int rbase = mtile * BM + mw * 32 + (lane >> 2);
    const int cbase = ntile * BN + nw * 64 + (lane & 3) * 2;
#pragma unroll
    for (int t = 0; t < 2; t++) {
        const int r0 = rbase + t * 16;
#pragma unroll
        for (int n = 0; n < 8; n++) {
            const int col = cbase + n * 8;
            const float2 bb = *reinterpret_cast<const float2*>(bias + col);
            float2 v0, v1;
            v0.x = acc[t][n][0] * scl + bb.x;
            v0.y = acc[t][n][1] * scl + bb.y;
            v1.x = acc[t][n][2] * scl + bb.x;
            v1.y = acc[t][n][3] * scl + bb.y;
            *reinterpret_cast<float2*>(out + (size_t)r0 * N_TOTAL + col) = v0;
            *reinterpret_cast<float2*>(out + (size_t)(r0 + 8) * N_TOTAL + col) = v1;
        }
    }
}

// ---------------- launch ----------------
extern "C" void kernel_launch(void* const* d_in, const int* in_sizes, int n_in,
                              void* d_out, int out_size) {
    (void)in_sizes; (void)n_in; (void)out_size;
    const float* x     = (const float*)d_in[0];
    const int*   w     = (const int*)  d_in[1];
    const float* scale = (const float*)d_in[2];
    const float* zp    = (const float*)d_in[3];
    const float* bias  = (const float*)d_in[4];
    float* out = (float*)d_out;

    cvt_all_kernel<<<(unsigned)(W_CHUNKS / 512), 256>>>((const float4*)x, (const int4*)w, zp);

    static int smem_set = 0;
    if (!smem_set) {
        cudaFuncSetAttribute(gemm_hmma_kernel,
                             cudaFuncAttributeMaxDynamicSharedMemorySize, SMEM_TOTAL);
        smem_set = 1;
    }
    dim3 grid(M_TOTAL / BM, N_TOTAL / BN);
    gemm_hmma_kernel<<<grid, 256, SMEM_TOTAL>>>(scale, bias, out);
}